// round 16
// baseline (speedup 1.0000x reference)
#include <cuda_runtime.h>

typedef unsigned long long u64;
typedef unsigned int u32;

#define B 32
#define N 2048
#define C 64
#define R 32
#define K 64

#define NB_PROD 128
#define NB_FROB 32
#define NB_M    4096
#define NB_TOTAL (NB_PROD + NB_FROB + NB_M)

__device__ u64 g_part[B * 4 * 64];   // 4 sorted top-64 lists per batch
__device__ u32 g_done = 0;           // producer completion counter
__device__ u32 g_exit = 0;           // block exit counter (for flag reset)

// Monotone key: descending value, ascending index, as one u64 (bigger = first).
__device__ __forceinline__ u64 make_key(float v, int idx) {
    u32 u = __float_as_uint(v);
    u = (u & 0x80000000u) ? ~u : (u | 0x80000000u);   // order-preserving f32->u32
    return ((u64)u << 32) | (u32)(N - 1 - idx);       // low word: smaller idx wins
}

__device__ __forceinline__ void unmake_key(u64 kk, float& v, int& id) {
    id = (N - 1) - (int)(kk & 0xffffffffu);
    u32 hu = (u32)(kk >> 32);
    u32 fb = (hu & 0x80000000u) ? (hu ^ 0x80000000u) : ~hu;
    v = __uint_as_float(fb);
}

__device__ __forceinline__ u32 ld_relaxed_gpu(const u32* p) {
    u32 v;
    asm volatile("ld.relaxed.gpu.u32 %0, [%1];" : "=r"(v) : "l"(p) : "memory");
    return v;
}

// Fence-based acquire of the producer flag (tid0 polls, fence, block barrier).
__device__ __forceinline__ void spin_done() {
    if (threadIdx.x == 0) {
        while (ld_relaxed_gpu(&g_done) < NB_PROD) __nanosleep(64);
        __threadfence();
    }
    __syncthreads();
}

// compare-exchange on packed keys; partner differs in lane bit j
__device__ __forceinline__ void cmpx64(u64& k, int j, bool desc) {
    u64 o = __shfl_xor_sync(0xffffffffu, k, j);
    bool keep_big = (((threadIdx.x & 31) & j) == 0) == desc;
    k = ((k > o) == keep_big) ? k : o;
}

// warp-level: sort 64 keys (2 per lane) descending
__device__ __forceinline__ void warp_sort64(u64& k0, u64& k1) {
    const int lane = threadIdx.x & 31;
    #pragma unroll
    for (int k = 2; k <= 32; k <<= 1) {
        #pragma unroll
        for (int j = k >> 1; j >= 1; j >>= 1) {
            cmpx64(k0, j, ((lane)      & k) == 0);
            cmpx64(k1, j, ((lane + 32) & k) == 0);
        }
    }
    if (!(k0 > k1)) { u64 t = k0; k0 = k1; k1 = t; }
    #pragma unroll
    for (int j = 16; j >= 1; j >>= 1) { cmpx64(k0, j, true); cmpx64(k1, j, true); }
}

// warp-level: top-64 of two sorted-desc 64-lists; result sorted-desc in a0/a1
__device__ __forceinline__ void warp_merge64(u64& a0, u64& a1, u64 b0, u64 b1) {
    u64 m0 = __shfl_xor_sync(0xffffffffu, b1, 31);   // B[63-e] for e=lane
    u64 m1 = __shfl_xor_sync(0xffffffffu, b0, 31);   // B[63-e] for e=lane+32
    if (m0 > a0) a0 = m0;
    if (m1 > a1) a1 = m1;
    if (!(a0 > a1)) { u64 t = a0; a0 = a1; a1 = t; }
    #pragma unroll
    for (int j = 16; j >= 1; j >>= 1) { cmpx64(a0, j, true); cmpx64(a1, j, true); }
}

// block-level: merge nlists sorted-desc 64-lists resident in sk -> top-64 in
// warp 0's (f0, f1). Race-safe: barrier between each round's loads and stores.
// ALL 256 threads of the block must call this.
__device__ __forceinline__ void block_merge(u64* sk, int nlists, u64& f0, u64& f1) {
    const int lane = threadIdx.x & 31;
    const int w    = threadIdx.x >> 5;
    for (int nw = nlists >> 1; nw >= 1; nw >>= 1) {
        u64 a0 = 0, a1 = 0, b0 = 0, b1 = 0;
        if (w < nw) {
            const int la = 2 * w, lb = 2 * w + 1;
            a0 = sk[la * 64 + lane];
            a1 = sk[la * 64 + 32 + lane];
            b0 = sk[lb * 64 + lane];
            b1 = sk[lb * 64 + 32 + lane];
        }
        __syncthreads();                  // all reads done before any write
        if (w < nw) {
            warp_merge64(a0, a1, b0, b1);
            if (nw > 1) {
                sk[w * 64 + lane]      = a0;
                sk[w * 64 + 32 + lane] = a1;
            } else { f0 = a0; f1 = a1; }
        }
        __syncthreads();                  // writes visible before next reads
    }
}

// load batch b's 4 sorted lists from g_part into sk (warps 0..3)
__device__ __forceinline__ void load_lists4(u64* sk, int b) {
    const int lane = threadIdx.x & 31;
    const int w    = threadIdx.x >> 5;
    if (w < 4) {
        sk[w * 64 + lane]      = g_part[(b * 4 + w) * 64 + lane];
        sk[w * 64 + 32 + lane] = g_part[(b * 4 + w) * 64 + 32 + lane];
    }
    __syncthreads();
}

// ---------------------------------------------------------------------------
// THE kernel. One launch, zero graph edges.
//   bid <  128      : producer — sort 512-elem chunk -> top-64 list -> g_part
//   bid in [128,160): frob+emit for batch bid-128 (spins on g_done)
//   bid >= 160      : M block (zero s_pv, spin, local merge, proven store loop)
// Producers occupy the lowest bids -> guaranteed wave-1 residency (no deadlock).
// ---------------------------------------------------------------------------
__global__ __launch_bounds__(256, 8)
void fused_kernel(const float* __restrict__ acc, const float* __restrict__ U,
                  float* __restrict__ out, float* __restrict__ outM) {
    __shared__ float s_pv[N];            // 8 KB (M blocks)
    __shared__ u64   sk[512];            // 4 KB merge scratch
    __shared__ float sv[K];              // frob blocks
    __shared__ int   si[K];

    const int bid  = blockIdx.x;
    const int tid  = threadIdx.x;
    const int lane = tid & 31;
    const int w    = tid >> 5;           // warp 0..7

    if (bid < NB_PROD) {
        // ---- producer: batch b, chunk c of 512 elements ----
        const int b = bid >> 2, c = bid & 3;
        const float* row = acc + b * N + c * 512;
        const int base = c * 512 + w * 64;
        u64 k0 = make_key(row[w * 64 + lane],      base + lane);
        u64 k1 = make_key(row[w * 64 + 32 + lane], base + 32 + lane);
        warp_sort64(k0, k1);
        sk[w * 64 + lane]      = k0;
        sk[w * 64 + 32 + lane] = k1;
        __syncthreads();

        u64 f0 = 0, f1 = 0;
        block_merge(sk, 8, f0, f1);      // 8 lists -> 1

        if (w == 0) {
            g_part[(b * 4 + c) * 64 + lane]      = f0;
            g_part[(b * 4 + c) * 64 + 32 + lane] = f1;
        }
        __threadfence();                 // stores gpu-visible before release
        __syncthreads();
        if (tid == 0) atomicAdd(&g_done, 1);

    } else if (bid < NB_PROD + NB_FROB) {
        // ---- frob + emit for batch b (hidden under the M store stream) ----
        const int b = bid - NB_PROD;
        spin_done();
        load_lists4(sk, b);
        u64 f0 = 0, f1 = 0;
        block_merge(sk, 4, f0, f1);

        if (w == 0) {
            #pragma unroll
            for (int h = 0; h < 2; h++) {
                float v; int id;
                unmake_key(h ? f1 : f0, v, id);
                int pos = lane + h * 32;
                out[b * K + pos]         = v;           // topk_vals
                out[B * K + b * K + pos] = (float)id;   // topk_idx
                sv[pos] = v;
                si[pos] = id;
            }
        }
        __syncthreads();

        // frob: warp w handles channels w*8 .. w*8+7; lane = r
        #pragma unroll
        for (int cc = 0; cc < 8; cc++) {
            const int ch = w * 8 + cc;
            const float* Uc = U + (size_t)ch * N * R;
            float au = 0.0f;
            #pragma unroll 8
            for (int k = 0; k < K; k++)
                au = fmaf(sv[k], __ldg(Uc + (size_t)si[k] * R + lane), au);
            float sq = au * au;
            #pragma unroll
            for (int o = 16; o > 0; o >>= 1)
                sq += __shfl_xor_sync(0xffffffffu, sq, o);
            if (lane == 0) out[2 * B * K + b * C + ch] = sq / (float)(K * R);
        }

    } else {
        // ---- M block: tile of 16 rows of batch b ----
        const int m    = bid - NB_PROD - NB_FROB;
        const int b    = m >> 7;         // 128 tiles per batch
        const int tile = m & 127;

        // zero s_pv before the spin (independent work overlaps producers)
        float4* s4f = reinterpret_cast<float4*>(s_pv);
        s4f[tid]       = make_float4(0.f, 0.f, 0.f, 0.f);
        s4f[tid + 256] = make_float4(0.f, 0.f, 0.f, 0.f);

        spin_done();
        load_lists4(sk, b);
        u64 f0 = 0, f1 = 0;
        block_merge(sk, 4, f0, f1);      // has barriers: orders zero vs scatter

        if (w == 0) {
            #pragma unroll
            for (int h = 0; h < 2; h++) {
                float v; int id;
                unmake_key(h ? f1 : f0, v, id);
                s_pv[id] = v;
            }
        }
        __syncthreads();

        // ---- proven store loop (76.5-76.9us @ ~78% DRAM) ----
        float4* out4 = reinterpret_cast<float4*>(outM);
        #pragma unroll
        for (int ir = 0; ir < 16; ir++) {
            const int i = tile * 16 + ir;
            const float pvi = s_pv[i];
            const size_t base = ((size_t)b * N + i) * (N / 4);
            #pragma unroll
            for (int jj = 0; jj < 2; jj++) {
                const int j4 = tid + jj * 256;
                float4 v = s4f[j4];
                float4 o = make_float4(pvi * v.x, pvi * v.y, pvi * v.z, pvi * v.w);
                __stcs(&out4[base + j4], o);
            }
        }
    }

    // ---- epilogue: last block out resets the flags for the next replay ----
    __syncthreads();
    if (tid == 0) {
        u32 t = atomicAdd(&g_exit, 1);
        if (t == NB_TOTAL - 1) {
            atomicExch(&g_done, 0);
            atomicExch(&g_exit, 0);
        }
    }
}

extern "C" void kernel_launch(void* const* d_in, const int* in_sizes, int n_in,
                              void* d_out, int out_size) {
    const float* acc = (const float*)d_in[0];   // [B, N] float32
    const float* U   = (const float*)d_in[1];   // [C, N, R] float32
    float* out  = (float*)d_out;
    float* outM = out + 3 * B * K;

    fused_kernel<<<NB_TOTAL, 256>>>(acc, U, out, outM);
}

// round 17
// speedup vs baseline: 1.0040x; 1.0040x over previous
#include <cuda_runtime.h>

typedef unsigned long long u64;
typedef unsigned int u32;

#define B 32
#define N 2048
#define C 64
#define R 32
#define K 64

#define NB_PROD 128
#define NB_FROB 32
#define NB_M    4096
#define NB_TOTAL (NB_PROD + NB_FROB + NB_M)

__device__ u64 g_part[B * 4 * 64];   // 4 sorted top-64 lists per batch
__device__ u32 g_doneb[B * 32];      // per-batch flag, padded to 128B lines
__device__ u32 g_exit = 0;           // block exit counter (for flag reset)

// Monotone key: descending value, ascending index, as one u64 (bigger = first).
__device__ __forceinline__ u64 make_key(float v, int idx) {
    u32 u = __float_as_uint(v);
    u = (u & 0x80000000u) ? ~u : (u | 0x80000000u);   // order-preserving f32->u32
    return ((u64)u << 32) | (u32)(N - 1 - idx);       // low word: smaller idx wins
}

__device__ __forceinline__ void unmake_key(u64 kk, float& v, int& id) {
    id = (N - 1) - (int)(kk & 0xffffffffu);
    u32 hu = (u32)(kk >> 32);
    u32 fb = (hu & 0x80000000u) ? (hu ^ 0x80000000u) : ~hu;
    v = __uint_as_float(fb);
}

__device__ __forceinline__ u32 ld_relaxed_gpu(const u32* p) {
    u32 v;
    asm volatile("ld.relaxed.gpu.u32 %0, [%1];" : "=r"(v) : "l"(p) : "memory");
    return v;
}

// Wait until all 4 producers of batch b released. tid0 polls its batch's
// PRIVATE flag line (32-way spread kills the R16 poll storm), then fences.
__device__ __forceinline__ void spin_batch(int b) {
    if (threadIdx.x == 0) {
        const u32* f = &g_doneb[b * 32];
        while (ld_relaxed_gpu(f) < 4u) __nanosleep(256);
        __threadfence();
    }
    __syncthreads();
}

// compare-exchange on packed keys; partner differs in lane bit j
__device__ __forceinline__ void cmpx64(u64& k, int j, bool desc) {
    u64 o = __shfl_xor_sync(0xffffffffu, k, j);
    bool keep_big = (((threadIdx.x & 31) & j) == 0) == desc;
    k = ((k > o) == keep_big) ? k : o;
}

// warp-level: sort 64 keys (2 per lane) descending
__device__ __forceinline__ void warp_sort64(u64& k0, u64& k1) {
    const int lane = threadIdx.x & 31;
    #pragma unroll
    for (int k = 2; k <= 32; k <<= 1) {
        #pragma unroll
        for (int j = k >> 1; j >= 1; j >>= 1) {
            cmpx64(k0, j, ((lane)      & k) == 0);
            cmpx64(k1, j, ((lane + 32) & k) == 0);
        }
    }
    if (!(k0 > k1)) { u64 t = k0; k0 = k1; k1 = t; }
    #pragma unroll
    for (int j = 16; j >= 1; j >>= 1) { cmpx64(k0, j, true); cmpx64(k1, j, true); }
}

// warp-level: top-64 of two sorted-desc 64-lists; result sorted-desc in a0/a1
__device__ __forceinline__ void warp_merge64(u64& a0, u64& a1, u64 b0, u64 b1) {
    u64 m0 = __shfl_xor_sync(0xffffffffu, b1, 31);   // B[63-e] for e=lane
    u64 m1 = __shfl_xor_sync(0xffffffffu, b0, 31);   // B[63-e] for e=lane+32
    if (m0 > a0) a0 = m0;
    if (m1 > a1) a1 = m1;
    if (!(a0 > a1)) { u64 t = a0; a0 = a1; a1 = t; }
    #pragma unroll
    for (int j = 16; j >= 1; j >>= 1) { cmpx64(a0, j, true); cmpx64(a1, j, true); }
}

// block-level: merge nlists sorted-desc 64-lists resident in sk -> top-64 in
// warp 0's (f0, f1). Race-safe: barrier between each round's loads and stores.
__device__ __forceinline__ void block_merge(u64* sk, int nlists, u64& f0, u64& f1) {
    const int lane = threadIdx.x & 31;
    const int w    = threadIdx.x >> 5;
    for (int nw = nlists >> 1; nw >= 1; nw >>= 1) {
        u64 a0 = 0, a1 = 0, b0 = 0, b1 = 0;
        if (w < nw) {
            const int la = 2 * w, lb = 2 * w + 1;
            a0 = sk[la * 64 + lane];
            a1 = sk[la * 64 + 32 + lane];
            b0 = sk[lb * 64 + lane];
            b1 = sk[lb * 64 + 32 + lane];
        }
        __syncthreads();                  // all reads done before any write
        if (w < nw) {
            warp_merge64(a0, a1, b0, b1);
            if (nw > 1) {
                sk[w * 64 + lane]      = a0;
                sk[w * 64 + 32 + lane] = a1;
            } else { f0 = a0; f1 = a1; }
        }
        __syncthreads();                  // writes visible before next reads
    }
}

// load batch b's 4 sorted lists from g_part into sk (warps 0..3)
__device__ __forceinline__ void load_lists4(u64* sk, int b) {
    const int lane = threadIdx.x & 31;
    const int w    = threadIdx.x >> 5;
    if (w < 4) {
        sk[w * 64 + lane]      = g_part[(b * 4 + w) * 64 + lane];
        sk[w * 64 + 32 + lane] = g_part[(b * 4 + w) * 64 + 32 + lane];
    }
    __syncthreads();
}

// ---------------------------------------------------------------------------
// THE kernel. One launch, zero graph edges, per-batch release/acquire.
//   bid <  128      : producer — sort 512-elem chunk -> top-64 list -> g_part
//   bid in [128,160): frob+emit for batch bid-128
//   bid >= 160      : M block (zero s_pv, spin, local merge, proven store loop)
// ---------------------------------------------------------------------------
__global__ __launch_bounds__(256, 8)
void fused_kernel(const float* __restrict__ acc, const float* __restrict__ U,
                  float* __restrict__ out, float* __restrict__ outM) {
    __shared__ float s_pv[N];            // 8 KB (M blocks)
    __shared__ u64   sk[512];            // 4 KB merge scratch
    __shared__ float sv[K];              // frob blocks
    __shared__ int   si[K];

    const int bid  = blockIdx.x;
    const int tid  = threadIdx.x;
    const int lane = tid & 31;
    const int w    = tid >> 5;           // warp 0..7

    if (bid < NB_PROD) {
        // ---- producer: batch b, chunk c of 512 elements ----
        const int b = bid >> 2, c = bid & 3;
        const float* row = acc + b * N + c * 512;
        const int base = c * 512 + w * 64;
        u64 k0 = make_key(row[w * 64 + lane],      base + lane);
        u64 k1 = make_key(row[w * 64 + 32 + lane], base + 32 + lane);
        warp_sort64(k0, k1);
        sk[w * 64 + lane]      = k0;
        sk[w * 64 + 32 + lane] = k1;
        __syncthreads();

        u64 f0 = 0, f1 = 0;
        block_merge(sk, 8, f0, f1);      // 8 lists -> 1

        if (w == 0) {
            g_part[(b * 4 + c) * 64 + lane]      = f0;
            g_part[(b * 4 + c) * 64 + 32 + lane] = f1;
        }
        __threadfence();                 // stores gpu-visible before release
        __syncthreads();
        if (tid == 0) atomicAdd(&g_doneb[b * 32], 1);   // private line per batch

    } else if (bid < NB_PROD + NB_FROB) {
        // ---- frob + emit for batch b (hidden under the M store stream) ----
        const int b = bid - NB_PROD;
        spin_batch(b);
        load_lists4(sk, b);
        u64 f0 = 0, f1 = 0;
        block_merge(sk, 4, f0, f1);

        if (w == 0) {
            #pragma unroll
            for (int h = 0; h < 2; h++) {
                float v; int id;
                unmake_key(h ? f1 : f0, v, id);
                int pos = lane + h * 32;
                out[b * K + pos]         = v;           // topk_vals
                out[B * K + b * K + pos] = (float)id;   // topk_idx
                sv[pos] = v;
                si[pos] = id;
            }
        }
        __syncthreads();

        // frob: warp w handles channels w*8 .. w*8+7; lane = r
        #pragma unroll
        for (int cc = 0; cc < 8; cc++) {
            const int ch = w * 8 + cc;
            const float* Uc = U + (size_t)ch * N * R;
            float au = 0.0f;
            #pragma unroll 8
            for (int k = 0; k < K; k++)
                au = fmaf(sv[k], __ldg(Uc + (size_t)si[k] * R + lane), au);
            float sq = au * au;
            #pragma unroll
            for (int o = 16; o > 0; o >>= 1)
                sq += __shfl_xor_sync(0xffffffffu, sq, o);
            if (lane == 0) out[2 * B * K + b * C + ch] = sq / (float)(K * R);
        }

    } else {
        // ---- M block: tile of 16 rows of batch b ----
        const int m    = bid - NB_PROD - NB_FROB;
        const int b    = m >> 7;         // 128 tiles per batch
        const int tile = m & 127;

        // zero s_pv before the spin (independent work overlaps producers)
        float4* s4f = reinterpret_cast<float4*>(s_pv);
        s4f[tid]       = make_float4(0.f, 0.f, 0.f, 0.f);
        s4f[tid + 256] = make_float4(0.f, 0.f, 0.f, 0.f);

        spin_batch(b);
        load_lists4(sk, b);
        u64 f0 = 0, f1 = 0;
        block_merge(sk, 4, f0, f1);      // barriers also order zero vs scatter

        if (w == 0) {
            #pragma unroll
            for (int h = 0; h < 2; h++) {
                float v; int id;
                unmake_key(h ? f1 : f0, v, id);
                s_pv[id] = v;
            }
        }
        __syncthreads();

        // ---- proven store loop (76.5-76.9us @ ~78% DRAM) ----
        float4* out4 = reinterpret_cast<float4*>(outM);
        #pragma unroll
        for (int ir = 0; ir < 16; ir++) {
            const int i = tile * 16 + ir;
            const float pvi = s_pv[i];
            const size_t base = ((size_t)b * N + i) * (N / 4);
            #pragma unroll
            for (int jj = 0; jj < 2; jj++) {
                const int j4 = tid + jj * 256;
                float4 v = s4f[j4];
                float4 o = make_float4(pvi * v.x, pvi * v.y, pvi * v.z, pvi * v.w);
                __stcs(&out4[base + j4], o);
            }
        }
    }

    // ---- epilogue: last block out resets the flags for the next replay ----
    __syncthreads();
    if (tid == 0) {
        u32 t = atomicAdd(&g_exit, 1);
        if (t == NB_TOTAL - 1) {
            #pragma unroll
            for (int bb = 0; bb < B; bb++) atomicExch(&g_doneb[bb * 32], 0);
            atomicExch(&g_exit, 0);
        }
    }
}

extern "C" void kernel_launch(void* const* d_in, const int* in_sizes, int n_in,
                              void* d_out, int out_size) {
    const float* acc = (const float*)d_in[0];   // [B, N] float32
    const float* U   = (const float*)d_in[1];   // [C, N, R] float32
    float* out  = (float*)d_out;
    float* outM = out + 3 * B * K;

    fused_kernel<<<NB_TOTAL, 256>>>(acc, U, out, outM);
}